// round 12
// baseline (speedup 1.0000x reference)
#include <cuda_runtime.h>
#include <cuda_fp16.h>
#include <cstdint>

#define NB 4
#define H  512
#define HP2 768            // padded column length, y in [-128, 639]
#define YOFF 128
#define W  360
#define D  512
#define HW (H*W)           // 184320
#define DD (D*D)           // 262144
#define QW 90              // angles per backproj CTA (4-way angle split)
#define KSL 4              // filter K-slices
#define KCH (H / KSL)      // 128 k per slice

// ---- device scratch (no allocations allowed) ----
__device__ float4 g_fpart[KSL][W * H];  // fp32 filter partials per K-slice
__device__ uint4  g_pkt[W * HP2];       // padded fp16 val+delta records
__device__ float  g_part[4][NB * DD];   // backproj partial sums per angle quarter

// ---- packed f32x2 helpers (FFMA2) ----
__device__ __forceinline__ unsigned long long pk2(float a, float b) {
    unsigned long long r;
    asm("mov.b64 %0, {%1, %2};" : "=l"(r) : "f"(a), "f"(b));
    return r;
}
__device__ __forceinline__ void upk2(unsigned long long v, float &a, float &b) {
    asm("mov.b64 {%0, %1}, %2;" : "=f"(a), "=f"(b) : "l"(v));
}
__device__ __forceinline__ void ffma2(unsigned long long &acc,
                                      unsigned long long a, unsigned long long b) {
    asm("fma.rn.f32x2 %0, %1, %2, %0;" : "+l"(acc) : "l"(a), "l"(b));
}
__device__ __forceinline__ __half2 u2h(unsigned u) { return *(__half2*)&u; }

// ============================================================
// Filter (K-split): C_z[i,c] = sum_{j in slice z} hG[(j-i-257)&511] * X[j,c]
// BM=64, BN=64, K=128/slice, grid (8,23,KSL)=736 CTAs.
// 256 thr, 4x4 per thread, FFMA2 core. fp32 partials to g_fpart[z].
// ============================================================
__global__ __launch_bounds__(256) void filter_kernel(const float* __restrict__ x,
                                                     const float* __restrict__ hG) {
    __shared__ float hs[512];
    __shared__ float Fs[16][64];
    __shared__ float Xs[16][64];

    int tid = threadIdx.x;
    hs[tid]       = hG[tid];
    hs[tid + 256] = hG[tid + 256];

    int tx = tid & 15;
    int ty = tid >> 4;
    int iblk = blockIdx.x * 64;
    int cblk = blockIdx.y * 64;
    int kbase = blockIdx.z * KCH;

    int lk  = ty;
    int lo4 = tx * 4;

    int wst = (cblk + lo4) >> 2;
    bool okw = (wst < W);
    const float* Xg = x + wst;

    int jb0 = -(iblk + lo4) - 257;

    __syncthreads();

    float4 fv;
    {
        int b = jb0 + kbase + lk;
        fv.x = hs[(b    ) & 511];
        fv.y = hs[(b - 1) & 511];
        fv.z = hs[(b - 2) & 511];
        fv.w = hs[(b - 3) & 511];
    }
    float xv0 = 0.f, xv1 = 0.f, xv2 = 0.f, xv3 = 0.f;
    if (okw) {
        xv0 = Xg[0 * HW + (kbase + lk) * W];
        xv1 = Xg[1 * HW + (kbase + lk) * W];
        xv2 = Xg[2 * HW + (kbase + lk) * W];
        xv3 = Xg[3 * HW + (kbase + lk) * W];
    }

    unsigned long long acc2[4][2] = {};

    for (int kk = 0; kk < KCH; kk += 16) {
        __syncthreads();
        *(float4*)&Fs[lk][lo4] = fv;
        Xs[lk][lo4 + 0] = xv0;
        Xs[lk][lo4 + 1] = xv1;
        Xs[lk][lo4 + 2] = xv2;
        Xs[lk][lo4 + 3] = xv3;
        __syncthreads();

        int kn = kk + 16;
        if (kn < KCH) {
            int b = jb0 + kbase + kn + lk;
            fv.x = hs[(b    ) & 511];
            fv.y = hs[(b - 1) & 511];
            fv.z = hs[(b - 2) & 511];
            fv.w = hs[(b - 3) & 511];
            if (okw) {
                xv0 = Xg[0 * HW + (kbase + kn + lk) * W];
                xv1 = Xg[1 * HW + (kbase + kn + lk) * W];
                xv2 = Xg[2 * HW + (kbase + kn + lk) * W];
                xv3 = Xg[3 * HW + (kbase + kn + lk) * W];
            }
        }

        #pragma unroll
        for (int k = 0; k < 16; ++k) {
            float4 a  = *(const float4*)&Fs[k][tx * 4];
            float4 b4 = *(const float4*)&Xs[k][ty * 4];
            unsigned long long b01 = pk2(b4.x, b4.y);
            unsigned long long b23 = pk2(b4.z, b4.w);
            unsigned long long ax = pk2(a.x, a.x);
            unsigned long long ay = pk2(a.y, a.y);
            unsigned long long az = pk2(a.z, a.z);
            unsigned long long aw = pk2(a.w, a.w);
            ffma2(acc2[0][0], ax, b01);  ffma2(acc2[0][1], ax, b23);
            ffma2(acc2[1][0], ay, b01);  ffma2(acc2[1][1], ay, b23);
            ffma2(acc2[2][0], az, b01);  ffma2(acc2[2][1], az, b23);
            ffma2(acc2[3][0], aw, b01);  ffma2(acc2[3][1], aw, b23);
        }
    }

    int wout = (cblk >> 2) + ty;
    if (wout < W) {
        float4* pout = g_fpart[blockIdx.z];
        #pragma unroll
        for (int ii = 0; ii < 4; ++ii) {
            float b0, b1, b2, b3;
            upk2(acc2[ii][0], b0, b1);
            upk2(acc2[ii][1], b2, b3);
            pout[wout * H + iblk + tx * 4 + ii] = make_float4(b0, b1, b2, b3);
        }
    }
}

// ============================================================
// Reduce: sum 4 K-slice partials; emit PADDED fp16 val+delta table.
// Record j = w*HP2 + h encodes y = h - YOFF:
//   val(y) = colsum(y) if y in [0,511] else 0
//   delta  = val(y+1) - val(y)
// Covers all boundary cases (y=-1 ramp-in, y=511 ramp-out, pads 0).
// ============================================================
__global__ __launch_bounds__(256) void reduce_pk_kernel() {
    int j = blockIdx.x * 256 + threadIdx.x;   // 0 .. W*HP2-1
    int lane = threadIdx.x & 31;
    int w = j / HP2;
    int h = j - w * HP2;
    int y = h - YOFF;

    float s0 = 0.f, s1 = 0.f, s2 = 0.f, s3 = 0.f;
    if ((unsigned)y < (unsigned)H) {
        int i = w * H + y;
        float4 a = g_fpart[0][i];
        float4 b = g_fpart[1][i];
        float4 c = g_fpart[2][i];
        float4 d = g_fpart[3][i];
        s0 = (a.x + b.x) + (c.x + d.x);
        s1 = (a.y + b.y) + (c.y + d.y);
        s2 = (a.z + b.z) + (c.z + d.z);
        s3 = (a.w + b.w) + (c.w + d.w);
    }

    // neighbor val(y+1) via shfl (lane 31 reloads)
    float n0 = __shfl_down_sync(0xffffffffu, s0, 1);
    float n1 = __shfl_down_sync(0xffffffffu, s1, 1);
    float n2 = __shfl_down_sync(0xffffffffu, s2, 1);
    float n3 = __shfl_down_sync(0xffffffffu, s3, 1);
    if (lane == 31) {
        int yn = y + 1;
        n0 = n1 = n2 = n3 = 0.f;
        if ((unsigned)yn < (unsigned)H) {
            int i = w * H + yn;
            float4 a = g_fpart[0][i];
            float4 b = g_fpart[1][i];
            float4 c = g_fpart[2][i];
            float4 d = g_fpart[3][i];
            n0 = (a.x + b.x) + (c.x + d.x);
            n1 = (a.y + b.y) + (c.y + d.y);
            n2 = (a.z + b.z) + (c.z + d.z);
            n3 = (a.w + b.w) + (c.w + d.w);
        }
    }

    __half2 v01 = __floats2half2_rn(s0, s1);
    __half2 v23 = __floats2half2_rn(s2, s3);
    __half2 e01 = __floats2half2_rn(n0 - s0, n1 - s1);
    __half2 e23 = __floats2half2_rn(n2 - s2, n3 - s3);
    g_pkt[j] = make_uint4(*(unsigned*)&v01, *(unsigned*)&v23,
                          *(unsigned*)&e01, *(unsigned*)&e23);
}

// ============================================================
// Backprojection: 32x32 tile, 4-way ANGLE SPLIT, NO smem staging:
// direct L1-cached LDG.128 from the padded table. No predicates,
// no barriers in the main loop. half2 pair-accum, fp32 flush /2 angles.
// ============================================================
__global__ __launch_bounds__(256) void backproj_kernel(const float* __restrict__ t_y) {
    __shared__ float4 scoef[QW];

    int tid  = threadIdx.x;
    int lane = tid & 31;
    int warp = tid >> 5;
    int lx = lane >> 2;       // 0..7
    int ly = lane & 3;        // 0..3

    int z  = blockIdx.z;
    int w0 = z * QW;

    if (tid < QW) {
        int w = w0 + tid;
        float cosv =  256.0f * __ldg(&t_y[w * DD + 256 * D + 257]);
        float sinv = -256.0f * __ldg(&t_y[w * DD + 257 * D + 256]);
        const float s = 255.5f / 256.0f;
        float A = -s * sinv;
        float B =  s * cosv;
        float C0 = 255.5f - 256.0f * B - 256.0f * A;
        scoef[tid] = make_float4(A, B, C0, A * 8.0f);
    }
    __syncthreads();

    int X0 = blockIdx.x * 32;
    int Y0 = blockIdx.y * 32;

    int Xt = X0 + lx;                 // + s*8 per slot
    int Yt = Y0 + warp * 4 + ly;
    float Xtf = (float)Xt, Ytf = (float)Yt;

    float acc[4][4] = {};             // [slot][batch]

    const uint4* tab = g_pkt + (w0 * HP2 + YOFF);

    for (int wl = 0; wl < QW; wl += 2) {
        float4 c0 = scoef[wl];
        float4 c1 = scoef[wl + 1];
        float py0 = fmaf(c0.x, Xtf, fmaf(c0.y, Ytf, c0.z));
        float py1 = fmaf(c1.x, Xtf, fmaf(c1.y, Ytf, c1.z));
        const uint4* col0 = tab + wl * HP2;
        const uint4* col1 = col0 + HP2;

        #pragma unroll
        for (int s = 0; s < 4; ++s) {
            int   ya = __float2int_rd(py0);
            float fa = py0 - (float)ya;
            uint4 qa = __ldg(&col0[ya]);
            __half2 fa2 = __floats2half2_rn(fa, fa);
            __half2 p01 = __hfma2(u2h(qa.z), fa2, u2h(qa.x));
            __half2 p23 = __hfma2(u2h(qa.w), fa2, u2h(qa.y));

            int   yb = __float2int_rd(py1);
            float fb = py1 - (float)yb;
            uint4 qb = __ldg(&col1[yb]);
            __half2 fb2 = __floats2half2_rn(fb, fb);
            p01 = __hadd2(p01, u2h(qb.x));
            p23 = __hadd2(p23, u2h(qb.y));
            p01 = __hfma2(u2h(qb.z), fb2, p01);
            p23 = __hfma2(u2h(qb.w), fb2, p23);

            float2 f01 = __half22float2(p01);
            float2 f23 = __half22float2(p23);
            acc[s][0] += f01.x;
            acc[s][1] += f01.y;
            acc[s][2] += f23.x;
            acc[s][3] += f23.y;
            py0 += c0.w;
            py1 += c1.w;
        }
    }

    float* pout = g_part[z];
    #pragma unroll
    for (int s = 0; s < 4; ++s) {
        int X = Xt + s * 8;
        int o = X * D + Yt;
        pout[0 * DD + o] = acc[s][0];
        pout[1 * DD + o] = acc[s][1];
        pout[2 * DD + o] = acc[s][2];
        pout[3 * DD + o] = acc[s][3];
    }
}

// ============================================================
// Combine: out = (p0 + p1 + p2 + p3) * scale   (float4)
// ============================================================
__global__ __launch_bounds__(256) void combine_kernel(float* __restrict__ out) {
    const float scale = 0.004363323129985824f;  // pi / 720
    int i = blockIdx.x * 256 + threadIdx.x;
    float4 a = ((const float4*)g_part[0])[i];
    float4 b = ((const float4*)g_part[1])[i];
    float4 c = ((const float4*)g_part[2])[i];
    float4 d = ((const float4*)g_part[3])[i];
    float4 r;
    r.x = ((a.x + b.x) + (c.x + d.x)) * scale;
    r.y = ((a.y + b.y) + (c.y + d.y)) * scale;
    r.z = ((a.z + b.z) + (c.z + d.z)) * scale;
    r.w = ((a.w + b.w) + (c.w + d.w)) * scale;
    ((float4*)out)[i] = r;
}

extern "C" void kernel_launch(void* const* d_in, const int* in_sizes, int n_in,
                              void* d_out, int out_size) {
    const float* radon = (const float*)d_in[0];
    const float* hG    = (const float*)d_in[1];
    const float* t_y   = (const float*)d_in[2];
    float* out = (float*)d_out;

    filter_kernel<<<dim3(8, 23, KSL), 256>>>(radon, hG);
    reduce_pk_kernel<<<(W * HP2) / 256, 256>>>();
    backproj_kernel<<<dim3(16, 16, 4), 256>>>(t_y);
    combine_kernel<<<(NB * DD / 4) / 256, 256>>>(out);
}

// round 13
// speedup vs baseline: 1.1057x; 1.1057x over previous
#include <cuda_runtime.h>
#include <cuda_fp16.h>
#include <cstdint>

#define NB 4
#define H  512
#define HP (H + 2)         // haloed column length (g in [-1, 512])
#define W  360
#define D  512
#define HW (H*W)           // 184320
#define DD (D*D)           // 262144
#define WLEN 76            // window for 64-wide X tiles (span <= 73)
#define NSTG 8
#define QW 90              // angles per backproj CTA (4-way angle split)
#define KSL 4              // filter K-slices
#define KCH (H / KSL)      // 128 k per slice

// ---- device scratch (no allocations allowed) ----
__device__ float4 g_fpart[KSL][W * H];  // fp32 filter partials per K-slice
__device__ uint4  g_pkt[W * HP];        // fp16 val+delta, haloed: {v01, v23, d01, d23}
__device__ float  g_part[4][NB * DD];   // backproj partial sums per angle quarter

// ---- packed f32x2 helpers (FFMA2) ----
__device__ __forceinline__ unsigned long long pk2(float a, float b) {
    unsigned long long r;
    asm("mov.b64 %0, {%1, %2};" : "=l"(r) : "f"(a), "f"(b));
    return r;
}
__device__ __forceinline__ void upk2(unsigned long long v, float &a, float &b) {
    asm("mov.b64 {%0, %1}, %2;" : "=f"(a), "=f"(b) : "l"(v));
}
__device__ __forceinline__ void ffma2(unsigned long long &acc,
                                      unsigned long long a, unsigned long long b) {
    asm("fma.rn.f32x2 %0, %1, %2, %0;" : "+l"(acc) : "l"(a), "l"(b));
}
__device__ __forceinline__ __half2 u2h(unsigned u) { return *(__half2*)&u; }

// ============================================================
// Filter (K-split): C_z[i,c] = sum_{j in slice z} hG[(j-i-257)&511] * X[j,c]
// BM=64, BN=64, K=128/slice, grid (8,23,KSL)=736 CTAs.
// 256 thr, 4x4 per thread, FFMA2 core. fp32 partials to g_fpart[z].
// ============================================================
__global__ __launch_bounds__(256) void filter_kernel(const float* __restrict__ x,
                                                     const float* __restrict__ hG) {
    __shared__ float hs[512];
    __shared__ float Fs[16][64];
    __shared__ float Xs[16][64];

    int tid = threadIdx.x;
    hs[tid]       = hG[tid];
    hs[tid + 256] = hG[tid + 256];

    int tx = tid & 15;
    int ty = tid >> 4;
    int iblk = blockIdx.x * 64;
    int cblk = blockIdx.y * 64;
    int kbase = blockIdx.z * KCH;

    int lk  = ty;
    int lo4 = tx * 4;

    int wst = (cblk + lo4) >> 2;
    bool okw = (wst < W);
    const float* Xg = x + wst;

    int jb0 = -(iblk + lo4) - 257;

    __syncthreads();

    float4 fv;
    {
        int b = jb0 + kbase + lk;
        fv.x = hs[(b    ) & 511];
        fv.y = hs[(b - 1) & 511];
        fv.z = hs[(b - 2) & 511];
        fv.w = hs[(b - 3) & 511];
    }
    float xv0 = 0.f, xv1 = 0.f, xv2 = 0.f, xv3 = 0.f;
    if (okw) {
        xv0 = Xg[0 * HW + (kbase + lk) * W];
        xv1 = Xg[1 * HW + (kbase + lk) * W];
        xv2 = Xg[2 * HW + (kbase + lk) * W];
        xv3 = Xg[3 * HW + (kbase + lk) * W];
    }

    unsigned long long acc2[4][2] = {};

    for (int kk = 0; kk < KCH; kk += 16) {
        __syncthreads();
        *(float4*)&Fs[lk][lo4] = fv;
        Xs[lk][lo4 + 0] = xv0;
        Xs[lk][lo4 + 1] = xv1;
        Xs[lk][lo4 + 2] = xv2;
        Xs[lk][lo4 + 3] = xv3;
        __syncthreads();

        int kn = kk + 16;
        if (kn < KCH) {
            int b = jb0 + kbase + kn + lk;
            fv.x = hs[(b    ) & 511];
            fv.y = hs[(b - 1) & 511];
            fv.z = hs[(b - 2) & 511];
            fv.w = hs[(b - 3) & 511];
            if (okw) {
                xv0 = Xg[0 * HW + (kbase + kn + lk) * W];
                xv1 = Xg[1 * HW + (kbase + kn + lk) * W];
                xv2 = Xg[2 * HW + (kbase + kn + lk) * W];
                xv3 = Xg[3 * HW + (kbase + kn + lk) * W];
            }
        }

        #pragma unroll
        for (int k = 0; k < 16; ++k) {
            float4 a  = *(const float4*)&Fs[k][tx * 4];
            float4 b4 = *(const float4*)&Xs[k][ty * 4];
            unsigned long long b01 = pk2(b4.x, b4.y);
            unsigned long long b23 = pk2(b4.z, b4.w);
            unsigned long long ax = pk2(a.x, a.x);
            unsigned long long ay = pk2(a.y, a.y);
            unsigned long long az = pk2(a.z, a.z);
            unsigned long long aw = pk2(a.w, a.w);
            ffma2(acc2[0][0], ax, b01);  ffma2(acc2[0][1], ax, b23);
            ffma2(acc2[1][0], ay, b01);  ffma2(acc2[1][1], ay, b23);
            ffma2(acc2[2][0], az, b01);  ffma2(acc2[2][1], az, b23);
            ffma2(acc2[3][0], aw, b01);  ffma2(acc2[3][1], aw, b23);
        }
    }

    int wout = (cblk >> 2) + ty;
    if (wout < W) {
        float4* pout = g_fpart[blockIdx.z];
        #pragma unroll
        for (int ii = 0; ii < 4; ++ii) {
            float b0, b1, b2, b3;
            upk2(acc2[ii][0], b0, b1);
            upk2(acc2[ii][1], b2, b3);
            pout[wout * H + iblk + tx * 4 + ii] = make_float4(b0, b1, b2, b3);
        }
    }
}

// ============================================================
// Reduce: sum 4 K-slice partials; emit haloed fp16 val+delta table.
//   g = -1 : {0, val[0]};  g in [0,510]: {val[g], val[g+1]-val[g]}
//   g = 511: {val[511], -val[511]};  g = 512: {0,0}
// Record for g stored at w*HP + 1 + g.
// ============================================================
__global__ __launch_bounds__(256) void reduce_pk_kernel() {
    int i = blockIdx.x * 256 + threadIdx.x;   // 0 .. W*H-1
    int lane = threadIdx.x & 31;
    int r = i & (H - 1);
    int w = i >> 9;

    float4 a = g_fpart[0][i];
    float4 b = g_fpart[1][i];
    float4 c = g_fpart[2][i];
    float4 d = g_fpart[3][i];
    float s0 = (a.x + b.x) + (c.x + d.x);
    float s1 = (a.y + b.y) + (c.y + d.y);
    float s2 = (a.z + b.z) + (c.z + d.z);
    float s3 = (a.w + b.w) + (c.w + d.w);

    float n0 = __shfl_down_sync(0xffffffffu, s0, 1);
    float n1 = __shfl_down_sync(0xffffffffu, s1, 1);
    float n2 = __shfl_down_sync(0xffffffffu, s2, 1);
    float n3 = __shfl_down_sync(0xffffffffu, s3, 1);
    if (lane == 31) {
        int j = (i + 1 < W * H) ? i + 1 : i;
        float4 a2 = g_fpart[0][j];
        float4 b2 = g_fpart[1][j];
        float4 c2 = g_fpart[2][j];
        float4 d2 = g_fpart[3][j];
        n0 = (a2.x + b2.x) + (c2.x + d2.x);
        n1 = (a2.y + b2.y) + (c2.y + d2.y);
        n2 = (a2.z + b2.z) + (c2.z + d2.z);
        n3 = (a2.w + b2.w) + (c2.w + d2.w);
    }

    bool edge = (r == H - 1);
    float d0 = edge ? -s0 : n0 - s0;
    float d1 = edge ? -s1 : n1 - s1;
    float d2f = edge ? -s2 : n2 - s2;
    float d3 = edge ? -s3 : n3 - s3;

    __half2 v01 = __floats2half2_rn(s0, s1);
    __half2 v23 = __floats2half2_rn(s2, s3);
    __half2 e01 = __floats2half2_rn(d0, d1);
    __half2 e23 = __floats2half2_rn(d2f, d3);
    g_pkt[w * HP + 1 + r] = make_uint4(*(unsigned*)&v01, *(unsigned*)&v23,
                                       *(unsigned*)&e01, *(unsigned*)&e23);

    if (r == 0) {
        __half2 z2 = __floats2half2_rn(0.f, 0.f);
        unsigned zu = *(unsigned*)&z2;
        g_pkt[w * HP + 0] = make_uint4(zu, zu, *(unsigned*)&v01, *(unsigned*)&v23);
    }
    if (edge) {
        g_pkt[w * HP + H + 1] = make_uint4(0u, 0u, 0u, 0u);
    }
}

// ============================================================
// Backprojection: 64(X)x32(Y) tile, 4-way ANGLE SPLIT (z=0..3).
// 8 X-slots/thread; haloed val+delta window; half2 pair-accum,
// fp32 flush per 2 angles; per-ring coef {A, B, C0-lo, 8A}.
// ============================================================
__device__ __forceinline__ void stage_pair(int wl, int tid, float X0f, float Y0f,
                                           const float4* scoef, float4* srb,
                                           uint4 (*sb)[WLEN], int w0) {
    if (tid < 2 * WLEN) {
        int a   = (tid >= WLEN) ? 1 : 0;
        int idx = tid - (a ? WLEN : 0);
        int wa  = wl + a;
        float4 cf = scoef[wa];
        float pymin = fmaf(cf.x, X0f, fmaf(cf.y, Y0f, cf.z)) + cf.w;
        int lo = __float2int_rd(pymin) - 1;
        if (idx == 0)
            srb[wa & (NSTG - 1)] = make_float4(cf.x, cf.y, cf.z - (float)lo,
                                               cf.x * 8.0f);
        int g = lo + idx + 1;                 // haloed table index
        unsigned ok = ((unsigned)g < (unsigned)HP) ? 16u : 0u;
        int gc = g < 0 ? 0 : (g > HP - 1 ? HP - 1 : g);
        const uint4* src = g_pkt + ((w0 + wa) * HP + gc);
        unsigned sa = (unsigned)__cvta_generic_to_shared(&sb[wa & (NSTG - 1)][idx]);
        asm volatile("cp.async.cg.shared.global [%0], [%1], 16, %2;\n"
                     :: "r"(sa), "l"(src), "r"(ok));
    }
    asm volatile("cp.async.commit_group;\n" ::: "memory");
}

__device__ __forceinline__ void bp_pair(const float4* __restrict__ srb, int wl,
                                        const uint4* __restrict__ b0,
                                        const uint4* __restrict__ b1,
                                        float Xtf, float Ytf,
                                        float acc[8][4]) {
    float4 c0 = srb[wl & (NSTG - 1)];
    float4 c1 = srb[(wl + 1) & (NSTG - 1)];
    float py0 = fmaf(c0.x, Xtf, fmaf(c0.y, Ytf, c0.z));
    float py1 = fmaf(c1.x, Xtf, fmaf(c1.y, Ytf, c1.z));

    #pragma unroll
    for (int s = 0; s < 8; ++s) {
        int   ya = __float2int_rd(py0);
        float fa = py0 - (float)ya;
        uint4 qa = b0[ya];
        __half2 fa2 = __floats2half2_rn(fa, fa);
        __half2 p01 = __hfma2(u2h(qa.z), fa2, u2h(qa.x));
        __half2 p23 = __hfma2(u2h(qa.w), fa2, u2h(qa.y));

        int   yb = __float2int_rd(py1);
        float fb = py1 - (float)yb;
        uint4 qb = b1[yb];
        __half2 fb2 = __floats2half2_rn(fb, fb);
        p01 = __hadd2(p01, u2h(qb.x));
        p23 = __hadd2(p23, u2h(qb.y));
        p01 = __hfma2(u2h(qb.z), fb2, p01);
        p23 = __hfma2(u2h(qb.w), fb2, p23);

        float2 f01 = __half22float2(p01);
        float2 f23 = __half22float2(p23);
        acc[s][0] += f01.x;
        acc[s][1] += f01.y;
        acc[s][2] += f23.x;
        acc[s][3] += f23.y;
        py0 += c0.w;
        py1 += c1.w;
    }
}

__global__ __launch_bounds__(256) void backproj_kernel(const float* __restrict__ t_y) {
    __shared__ float4 scoef[QW];
    __shared__ float4 srb[NSTG];
    __shared__ uint4  sb[NSTG][WLEN];

    int tid  = threadIdx.x;
    int lane = tid & 31;
    int warp = tid >> 5;
    int lx = lane >> 2;       // 0..7
    int ly = lane & 3;        // 0..3

    int z  = blockIdx.z;
    int w0 = z * QW;

    if (tid < QW) {
        int w = w0 + tid;
        float cosv =  256.0f * __ldg(&t_y[w * DD + 256 * D + 257]);
        float sinv = -256.0f * __ldg(&t_y[w * DD + 257 * D + 256]);
        const float s = 255.5f / 256.0f;
        float A = -s * sinv;
        float B =  s * cosv;
        float C0 = 255.5f - 256.0f * B - 256.0f * A;
        float minAB = fminf(A * 63.0f, 0.0f) + fminf(B * 31.0f, 0.0f);
        scoef[tid] = make_float4(A, B, C0, minAB);
    }
    __syncthreads();

    int X0 = blockIdx.x * 64;
    int Y0 = blockIdx.y * 32;
    float X0f = (float)X0, Y0f = (float)Y0;

    int Xt = X0 + lx;                 // + s*8 per slot, s=0..7
    int Yt = Y0 + warp * 4 + ly;
    float Xtf = (float)Xt, Ytf = (float)Yt;

    float acc[8][4] = {};             // [slot][batch]

    stage_pair(0, tid, X0f, Y0f, scoef, srb, sb, w0);
    stage_pair(2, tid, X0f, Y0f, scoef, srb, sb, w0);
    stage_pair(4, tid, X0f, Y0f, scoef, srb, sb, w0);

    for (int wl = 0; wl < QW; wl += 2) {
        asm volatile("cp.async.wait_group 2;\n" ::: "memory");
        __syncthreads();

        int wn = wl + 6;
        if (wn < QW) {
            stage_pair(wn, tid, X0f, Y0f, scoef, srb, sb, w0);
        } else {
            asm volatile("cp.async.commit_group;\n" ::: "memory");
        }

        bp_pair(srb, wl, sb[wl & (NSTG - 1)], sb[(wl + 1) & (NSTG - 1)],
                Xtf, Ytf, acc);
    }

    float* pout = g_part[z];
    #pragma unroll
    for (int s = 0; s < 8; ++s) {
        int X = Xt + s * 8;
        int o = X * D + Yt;
        pout[0 * DD + o] = acc[s][0];
        pout[1 * DD + o] = acc[s][1];
        pout[2 * DD + o] = acc[s][2];
        pout[3 * DD + o] = acc[s][3];
    }
}

// ============================================================
// Combine: out = (p0 + p1 + p2 + p3) * scale   (float4)
// ============================================================
__global__ __launch_bounds__(256) void combine_kernel(float* __restrict__ out) {
    const float scale = 0.004363323129985824f;  // pi / 720
    int i = blockIdx.x * 256 + threadIdx.x;
    float4 a = ((const float4*)g_part[0])[i];
    float4 b = ((const float4*)g_part[1])[i];
    float4 c = ((const float4*)g_part[2])[i];
    float4 d = ((const float4*)g_part[3])[i];
    float4 r;
    r.x = ((a.x + b.x) + (c.x + d.x)) * scale;
    r.y = ((a.y + b.y) + (c.y + d.y)) * scale;
    r.z = ((a.z + b.z) + (c.z + d.z)) * scale;
    r.w = ((a.w + b.w) + (c.w + d.w)) * scale;
    ((float4*)out)[i] = r;
}

extern "C" void kernel_launch(void* const* d_in, const int* in_sizes, int n_in,
                              void* d_out, int out_size) {
    const float* radon = (const float*)d_in[0];
    const float* hG    = (const float*)d_in[1];
    const float* t_y   = (const float*)d_in[2];
    float* out = (float*)d_out;

    filter_kernel<<<dim3(8, 23, KSL), 256>>>(radon, hG);
    reduce_pk_kernel<<<(W * H) / 256, 256>>>();
    backproj_kernel<<<dim3(8, 16, 4), 256>>>(t_y);
    combine_kernel<<<(NB * DD / 4) / 256, 256>>>(out);
}

// round 14
// speedup vs baseline: 1.2242x; 1.1071x over previous
#include <cuda_runtime.h>
#include <cuda_fp16.h>
#include <cstdint>

#define NB 4
#define H  512
#define HP (H + 2)         // haloed column length (g in [-1, 512])
#define W  360
#define D  512
#define HW (H*W)           // 184320
#define DD (D*D)           // 262144
#define WLEN 48
#define NSTG 16            // ring buffers (groups of 4, 3 groups live max)
#define QW 90              // angles per backproj CTA (4-way angle split)
#define KSL 4              // filter K-slices
#define KCH (H / KSL)      // 128 k per slice

// ---- device scratch (no allocations allowed) ----
__device__ float4 g_fpart[KSL][W * H];  // fp32 filter partials per K-slice
__device__ uint4  g_pkt[W * HP];        // fp16 val+delta, haloed: {v01, v23, d01, d23}
__device__ float  g_part[4][NB * DD];   // backproj partial sums per angle quarter

// ---- packed f32x2 helpers (FFMA2) ----
__device__ __forceinline__ unsigned long long pk2(float a, float b) {
    unsigned long long r;
    asm("mov.b64 %0, {%1, %2};" : "=l"(r) : "f"(a), "f"(b));
    return r;
}
__device__ __forceinline__ void upk2(unsigned long long v, float &a, float &b) {
    asm("mov.b64 {%0, %1}, %2;" : "=f"(a), "=f"(b) : "l"(v));
}
__device__ __forceinline__ void ffma2(unsigned long long &acc,
                                      unsigned long long a, unsigned long long b) {
    asm("fma.rn.f32x2 %0, %1, %2, %0;" : "+l"(acc) : "l"(a), "l"(b));
}
__device__ __forceinline__ __half2 u2h(unsigned u) { return *(__half2*)&u; }

// ============================================================
// Filter (K-split): C_z[i,c] = sum_{j in slice z} hG[(j-i-257)&511] * X[j,c]
// BM=64, BN=64, K=128/slice, grid (8,23,KSL)=736 CTAs.
// ============================================================
__global__ __launch_bounds__(256) void filter_kernel(const float* __restrict__ x,
                                                     const float* __restrict__ hG) {
    __shared__ float hs[512];
    __shared__ float Fs[16][64];
    __shared__ float Xs[16][64];

    int tid = threadIdx.x;
    hs[tid]       = hG[tid];
    hs[tid + 256] = hG[tid + 256];

    int tx = tid & 15;
    int ty = tid >> 4;
    int iblk = blockIdx.x * 64;
    int cblk = blockIdx.y * 64;
    int kbase = blockIdx.z * KCH;

    int lk  = ty;
    int lo4 = tx * 4;

    int wst = (cblk + lo4) >> 2;
    bool okw = (wst < W);
    const float* Xg = x + wst;

    int jb0 = -(iblk + lo4) - 257;

    __syncthreads();

    float4 fv;
    {
        int b = jb0 + kbase + lk;
        fv.x = hs[(b    ) & 511];
        fv.y = hs[(b - 1) & 511];
        fv.z = hs[(b - 2) & 511];
        fv.w = hs[(b - 3) & 511];
    }
    float xv0 = 0.f, xv1 = 0.f, xv2 = 0.f, xv3 = 0.f;
    if (okw) {
        xv0 = Xg[0 * HW + (kbase + lk) * W];
        xv1 = Xg[1 * HW + (kbase + lk) * W];
        xv2 = Xg[2 * HW + (kbase + lk) * W];
        xv3 = Xg[3 * HW + (kbase + lk) * W];
    }

    unsigned long long acc2[4][2] = {};

    for (int kk = 0; kk < KCH; kk += 16) {
        __syncthreads();
        *(float4*)&Fs[lk][lo4] = fv;
        Xs[lk][lo4 + 0] = xv0;
        Xs[lk][lo4 + 1] = xv1;
        Xs[lk][lo4 + 2] = xv2;
        Xs[lk][lo4 + 3] = xv3;
        __syncthreads();

        int kn = kk + 16;
        if (kn < KCH) {
            int b = jb0 + kbase + kn + lk;
            fv.x = hs[(b    ) & 511];
            fv.y = hs[(b - 1) & 511];
            fv.z = hs[(b - 2) & 511];
            fv.w = hs[(b - 3) & 511];
            if (okw) {
                xv0 = Xg[0 * HW + (kbase + kn + lk) * W];
                xv1 = Xg[1 * HW + (kbase + kn + lk) * W];
                xv2 = Xg[2 * HW + (kbase + kn + lk) * W];
                xv3 = Xg[3 * HW + (kbase + kn + lk) * W];
            }
        }

        #pragma unroll
        for (int k = 0; k < 16; ++k) {
            float4 a  = *(const float4*)&Fs[k][tx * 4];
            float4 b4 = *(const float4*)&Xs[k][ty * 4];
            unsigned long long b01 = pk2(b4.x, b4.y);
            unsigned long long b23 = pk2(b4.z, b4.w);
            unsigned long long ax = pk2(a.x, a.x);
            unsigned long long ay = pk2(a.y, a.y);
            unsigned long long az = pk2(a.z, a.z);
            unsigned long long aw = pk2(a.w, a.w);
            ffma2(acc2[0][0], ax, b01);  ffma2(acc2[0][1], ax, b23);
            ffma2(acc2[1][0], ay, b01);  ffma2(acc2[1][1], ay, b23);
            ffma2(acc2[2][0], az, b01);  ffma2(acc2[2][1], az, b23);
            ffma2(acc2[3][0], aw, b01);  ffma2(acc2[3][1], aw, b23);
        }
    }

    int wout = (cblk >> 2) + ty;
    if (wout < W) {
        float4* pout = g_fpart[blockIdx.z];
        #pragma unroll
        for (int ii = 0; ii < 4; ++ii) {
            float b0, b1, b2, b3;
            upk2(acc2[ii][0], b0, b1);
            upk2(acc2[ii][1], b2, b3);
            pout[wout * H + iblk + tx * 4 + ii] = make_float4(b0, b1, b2, b3);
        }
    }
}

// ============================================================
// Reduce: sum 4 K-slice partials; emit haloed fp16 val+delta table.
//   g = -1 : {0, val[0]};  g in [0,510]: {val[g], val[g+1]-val[g]}
//   g = 511: {val[511], -val[511]};  g = 512: {0,0}
// ============================================================
__global__ __launch_bounds__(256) void reduce_pk_kernel() {
    int i = blockIdx.x * 256 + threadIdx.x;   // 0 .. W*H-1
    int lane = threadIdx.x & 31;
    int r = i & (H - 1);
    int w = i >> 9;

    float4 a = g_fpart[0][i];
    float4 b = g_fpart[1][i];
    float4 c = g_fpart[2][i];
    float4 d = g_fpart[3][i];
    float s0 = (a.x + b.x) + (c.x + d.x);
    float s1 = (a.y + b.y) + (c.y + d.y);
    float s2 = (a.z + b.z) + (c.z + d.z);
    float s3 = (a.w + b.w) + (c.w + d.w);

    float n0 = __shfl_down_sync(0xffffffffu, s0, 1);
    float n1 = __shfl_down_sync(0xffffffffu, s1, 1);
    float n2 = __shfl_down_sync(0xffffffffu, s2, 1);
    float n3 = __shfl_down_sync(0xffffffffu, s3, 1);
    if (lane == 31) {
        int j = (i + 1 < W * H) ? i + 1 : i;
        float4 a2 = g_fpart[0][j];
        float4 b2 = g_fpart[1][j];
        float4 c2 = g_fpart[2][j];
        float4 d2 = g_fpart[3][j];
        n0 = (a2.x + b2.x) + (c2.x + d2.x);
        n1 = (a2.y + b2.y) + (c2.y + d2.y);
        n2 = (a2.z + b2.z) + (c2.z + d2.z);
        n3 = (a2.w + b2.w) + (c2.w + d2.w);
    }

    bool edge = (r == H - 1);
    float d0 = edge ? -s0 : n0 - s0;
    float d1 = edge ? -s1 : n1 - s1;
    float d2f = edge ? -s2 : n2 - s2;
    float d3 = edge ? -s3 : n3 - s3;

    __half2 v01 = __floats2half2_rn(s0, s1);
    __half2 v23 = __floats2half2_rn(s2, s3);
    __half2 e01 = __floats2half2_rn(d0, d1);
    __half2 e23 = __floats2half2_rn(d2f, d3);
    g_pkt[w * HP + 1 + r] = make_uint4(*(unsigned*)&v01, *(unsigned*)&v23,
                                       *(unsigned*)&e01, *(unsigned*)&e23);

    if (r == 0) {
        __half2 z2 = __floats2half2_rn(0.f, 0.f);
        unsigned zu = *(unsigned*)&z2;
        g_pkt[w * HP + 0] = make_uint4(zu, zu, *(unsigned*)&v01, *(unsigned*)&v23);
    }
    if (edge) {
        g_pkt[w * HP + H + 1] = make_uint4(0u, 0u, 0u, 0u);
    }
}

// ============================================================
// Backprojection: 32x32 tile, 4-way ANGLE SPLIT, 4 angles/barrier.
// 16-buffer ring (3 groups of 4 live). half2 pair-accum, fp32
// flush per 2 angles. Per-ring coef {A, B, C0-lo, 8A}.
// ============================================================
__device__ __forceinline__ void stage_group(int wbase, int tid, float X0f, float Y0f,
                                            const float4* scoef, float4* srb,
                                            uint4 (*sb)[WLEN], int w0) {
    int cnt = QW - wbase;
    if (cnt > 4) cnt = 4;
    if (cnt > 0 && tid < cnt * WLEN) {
        int a   = tid / WLEN;            // 0..3
        int idx = tid - a * WLEN;
        int wa  = wbase + a;
        float4 cf = scoef[wa];
        float pymin = fmaf(cf.x, X0f, fmaf(cf.y, Y0f, cf.z)) + cf.w;
        int lo = __float2int_rd(pymin) - 1;
        if (idx == 0)
            srb[wa & (NSTG - 1)] = make_float4(cf.x, cf.y, cf.z - (float)lo,
                                               cf.x * 8.0f);
        int g = lo + idx + 1;            // haloed table index
        unsigned ok = ((unsigned)g < (unsigned)HP) ? 16u : 0u;
        int gc = g < 0 ? 0 : (g > HP - 1 ? HP - 1 : g);
        const uint4* src = g_pkt + ((w0 + wa) * HP + gc);
        unsigned sa = (unsigned)__cvta_generic_to_shared(&sb[wa & (NSTG - 1)][idx]);
        asm volatile("cp.async.cg.shared.global [%0], [%1], 16, %2;\n"
                     :: "r"(sa), "l"(src), "r"(ok));
    }
    asm volatile("cp.async.commit_group;\n" ::: "memory");
}

__device__ __forceinline__ void bp_pair(const float4* __restrict__ srb, int wl,
                                        const uint4* __restrict__ b0,
                                        const uint4* __restrict__ b1,
                                        float Xtf, float Ytf,
                                        float acc[4][4]) {
    float4 c0 = srb[wl & (NSTG - 1)];
    float4 c1 = srb[(wl + 1) & (NSTG - 1)];
    float py0 = fmaf(c0.x, Xtf, fmaf(c0.y, Ytf, c0.z));
    float py1 = fmaf(c1.x, Xtf, fmaf(c1.y, Ytf, c1.z));

    #pragma unroll
    for (int s = 0; s < 4; ++s) {
        int   ya = __float2int_rd(py0);
        float fa = py0 - (float)ya;
        uint4 qa = b0[ya];
        __half2 fa2 = __floats2half2_rn(fa, fa);
        __half2 p01 = __hfma2(u2h(qa.z), fa2, u2h(qa.x));
        __half2 p23 = __hfma2(u2h(qa.w), fa2, u2h(qa.y));

        int   yb = __float2int_rd(py1);
        float fb = py1 - (float)yb;
        uint4 qb = b1[yb];
        __half2 fb2 = __floats2half2_rn(fb, fb);
        p01 = __hadd2(p01, u2h(qb.x));
        p23 = __hadd2(p23, u2h(qb.y));
        p01 = __hfma2(u2h(qb.z), fb2, p01);
        p23 = __hfma2(u2h(qb.w), fb2, p23);

        float2 f01 = __half22float2(p01);
        float2 f23 = __half22float2(p23);
        acc[s][0] += f01.x;
        acc[s][1] += f01.y;
        acc[s][2] += f23.x;
        acc[s][3] += f23.y;
        py0 += c0.w;
        py1 += c1.w;
    }
}

__global__ __launch_bounds__(256) void backproj_kernel(const float* __restrict__ t_y) {
    __shared__ float4 scoef[QW];
    __shared__ float4 srb[NSTG];
    __shared__ uint4  sb[NSTG][WLEN];

    int tid  = threadIdx.x;
    int lane = tid & 31;
    int warp = tid >> 5;
    int lx = lane >> 2;       // 0..7
    int ly = lane & 3;        // 0..3

    int z  = blockIdx.z;
    int w0 = z * QW;

    if (tid < QW) {
        int w = w0 + tid;
        float cosv =  256.0f * __ldg(&t_y[w * DD + 256 * D + 257]);
        float sinv = -256.0f * __ldg(&t_y[w * DD + 257 * D + 256]);
        const float s = 255.5f / 256.0f;
        float A = -s * sinv;
        float B =  s * cosv;
        float C0 = 255.5f - 256.0f * B - 256.0f * A;
        float minAB = fminf(A * 31.0f, 0.0f) + fminf(B * 31.0f, 0.0f);
        scoef[tid] = make_float4(A, B, C0, minAB);
    }
    __syncthreads();

    int X0 = blockIdx.x * 32;
    int Y0 = blockIdx.y * 32;
    float X0f = (float)X0, Y0f = (float)Y0;

    int Xt = X0 + lx;                 // + s*8 per slot
    int Yt = Y0 + warp * 4 + ly;
    float Xtf = (float)Xt, Ytf = (float)Yt;

    float acc[4][4] = {};             // [slot][batch]

    // prologue: stage groups (0-3), (4-7)
    stage_group(0, tid, X0f, Y0f, scoef, srb, sb, w0);
    stage_group(4, tid, X0f, Y0f, scoef, srb, sb, w0);

    // main loop: 22 iterations x 4 angles (covers 0..87)
    for (int wl = 0; wl < 88; wl += 4) {
        asm volatile("cp.async.wait_group 1;\n" ::: "memory");
        __syncthreads();

        stage_group(wl + 8, tid, X0f, Y0f, scoef, srb, sb, w0);

        bp_pair(srb, wl,     sb[wl & (NSTG - 1)], sb[(wl + 1) & (NSTG - 1)],
                Xtf, Ytf, acc);
        bp_pair(srb, wl + 2, sb[(wl + 2) & (NSTG - 1)], sb[(wl + 3) & (NSTG - 1)],
                Xtf, Ytf, acc);
    }

    // epilogue: angles 88, 89
    asm volatile("cp.async.wait_group 0;\n" ::: "memory");
    __syncthreads();
    bp_pair(srb, 88, sb[88 & (NSTG - 1)], sb[89 & (NSTG - 1)], Xtf, Ytf, acc);

    float* pout = g_part[z];
    #pragma unroll
    for (int s = 0; s < 4; ++s) {
        int X = Xt + s * 8;
        int o = X * D + Yt;
        pout[0 * DD + o] = acc[s][0];
        pout[1 * DD + o] = acc[s][1];
        pout[2 * DD + o] = acc[s][2];
        pout[3 * DD + o] = acc[s][3];
    }
}

// ============================================================
// Combine: out = (p0 + p1 + p2 + p3) * scale   (float4)
// ============================================================
__global__ __launch_bounds__(256) void combine_kernel(float* __restrict__ out) {
    const float scale = 0.004363323129985824f;  // pi / 720
    int i = blockIdx.x * 256 + threadIdx.x;
    float4 a = ((const float4*)g_part[0])[i];
    float4 b = ((const float4*)g_part[1])[i];
    float4 c = ((const float4*)g_part[2])[i];
    float4 d = ((const float4*)g_part[3])[i];
    float4 r;
    r.x = ((a.x + b.x) + (c.x + d.x)) * scale;
    r.y = ((a.y + b.y) + (c.y + d.y)) * scale;
    r.z = ((a.z + b.z) + (c.z + d.z)) * scale;
    r.w = ((a.w + b.w) + (c.w + d.w)) * scale;
    ((float4*)out)[i] = r;
}

extern "C" void kernel_launch(void* const* d_in, const int* in_sizes, int n_in,
                              void* d_out, int out_size) {
    const float* radon = (const float*)d_in[0];
    const float* hG    = (const float*)d_in[1];
    const float* t_y   = (const float*)d_in[2];
    float* out = (float*)d_out;

    filter_kernel<<<dim3(8, 23, KSL), 256>>>(radon, hG);
    reduce_pk_kernel<<<(W * H) / 256, 256>>>();
    backproj_kernel<<<dim3(16, 16, 4), 256>>>(t_y);
    combine_kernel<<<(NB * DD / 4) / 256, 256>>>(out);
}

// round 15
// speedup vs baseline: 1.2368x; 1.0103x over previous
#include <cuda_runtime.h>
#include <cuda_fp16.h>
#include <cstdint>

#define NB 4
#define H  512
#define HP (H + 2)         // haloed column length (g in [-1, 512])
#define W  360
#define D  512
#define HW (H*W)           // 184320
#define DD (D*D)           // 262144
#define WLEN 48
#define NSTG 16            // ring buffers (groups of 4, 3 groups live max)
#define QW 90              // angles per backproj CTA (4-way angle split)
#define KSL 4              // filter K-slices
#define KCH (H / KSL)      // 128 k per slice

// ---- device scratch (no allocations allowed) ----
__device__ float4 g_fpart[KSL][W * H];  // fp32 filter partials per K-slice
__device__ uint4  g_pkt[W * HP];        // fp16 val+delta, haloed: {v01, v23, d01, d23}
__device__ float  g_part[4][NB * DD];   // backproj partial sums per angle quarter

// ---- packed f32x2 helpers (FFMA2) ----
__device__ __forceinline__ unsigned long long pk2(float a, float b) {
    unsigned long long r;
    asm("mov.b64 %0, {%1, %2};" : "=l"(r) : "f"(a), "f"(b));
    return r;
}
__device__ __forceinline__ void upk2(unsigned long long v, float &a, float &b) {
    asm("mov.b64 {%0, %1}, %2;" : "=f"(a), "=f"(b) : "l"(v));
}
__device__ __forceinline__ void ffma2(unsigned long long &acc,
                                      unsigned long long a, unsigned long long b) {
    asm("fma.rn.f32x2 %0, %1, %2, %0;" : "+l"(acc) : "l"(a), "l"(b));
}
__device__ __forceinline__ __half2 u2h(unsigned u) { return *(__half2*)&u; }

// ============================================================
// Filter (K-split): C_z[i,c] = sum_{j in slice z} hG[(j-i-257)&511] * X[j,c]
// BM=64, BN=64, K=128/slice, grid (8,23,KSL)=736 CTAs.
// ============================================================
__global__ __launch_bounds__(256) void filter_kernel(const float* __restrict__ x,
                                                     const float* __restrict__ hG) {
    __shared__ float hs[512];
    __shared__ float Fs[16][64];
    __shared__ float Xs[16][64];

    int tid = threadIdx.x;
    hs[tid]       = hG[tid];
    hs[tid + 256] = hG[tid + 256];

    int tx = tid & 15;
    int ty = tid >> 4;
    int iblk = blockIdx.x * 64;
    int cblk = blockIdx.y * 64;
    int kbase = blockIdx.z * KCH;

    int lk  = ty;
    int lo4 = tx * 4;

    int wst = (cblk + lo4) >> 2;
    bool okw = (wst < W);
    const float* Xg = x + wst;

    int jb0 = -(iblk + lo4) - 257;

    __syncthreads();

    float4 fv;
    {
        int b = jb0 + kbase + lk;
        fv.x = hs[(b    ) & 511];
        fv.y = hs[(b - 1) & 511];
        fv.z = hs[(b - 2) & 511];
        fv.w = hs[(b - 3) & 511];
    }
    float xv0 = 0.f, xv1 = 0.f, xv2 = 0.f, xv3 = 0.f;
    if (okw) {
        xv0 = Xg[0 * HW + (kbase + lk) * W];
        xv1 = Xg[1 * HW + (kbase + lk) * W];
        xv2 = Xg[2 * HW + (kbase + lk) * W];
        xv3 = Xg[3 * HW + (kbase + lk) * W];
    }

    unsigned long long acc2[4][2] = {};

    for (int kk = 0; kk < KCH; kk += 16) {
        __syncthreads();
        *(float4*)&Fs[lk][lo4] = fv;
        Xs[lk][lo4 + 0] = xv0;
        Xs[lk][lo4 + 1] = xv1;
        Xs[lk][lo4 + 2] = xv2;
        Xs[lk][lo4 + 3] = xv3;
        __syncthreads();

        int kn = kk + 16;
        if (kn < KCH) {
            int b = jb0 + kbase + kn + lk;
            fv.x = hs[(b    ) & 511];
            fv.y = hs[(b - 1) & 511];
            fv.z = hs[(b - 2) & 511];
            fv.w = hs[(b - 3) & 511];
            if (okw) {
                xv0 = Xg[0 * HW + (kbase + kn + lk) * W];
                xv1 = Xg[1 * HW + (kbase + kn + lk) * W];
                xv2 = Xg[2 * HW + (kbase + kn + lk) * W];
                xv3 = Xg[3 * HW + (kbase + kn + lk) * W];
            }
        }

        #pragma unroll
        for (int k = 0; k < 16; ++k) {
            float4 a  = *(const float4*)&Fs[k][tx * 4];
            float4 b4 = *(const float4*)&Xs[k][ty * 4];
            unsigned long long b01 = pk2(b4.x, b4.y);
            unsigned long long b23 = pk2(b4.z, b4.w);
            unsigned long long ax = pk2(a.x, a.x);
            unsigned long long ay = pk2(a.y, a.y);
            unsigned long long az = pk2(a.z, a.z);
            unsigned long long aw = pk2(a.w, a.w);
            ffma2(acc2[0][0], ax, b01);  ffma2(acc2[0][1], ax, b23);
            ffma2(acc2[1][0], ay, b01);  ffma2(acc2[1][1], ay, b23);
            ffma2(acc2[2][0], az, b01);  ffma2(acc2[2][1], az, b23);
            ffma2(acc2[3][0], aw, b01);  ffma2(acc2[3][1], aw, b23);
        }
    }

    int wout = (cblk >> 2) + ty;
    if (wout < W) {
        float4* pout = g_fpart[blockIdx.z];
        #pragma unroll
        for (int ii = 0; ii < 4; ++ii) {
            float b0, b1, b2, b3;
            upk2(acc2[ii][0], b0, b1);
            upk2(acc2[ii][1], b2, b3);
            pout[wout * H + iblk + tx * 4 + ii] = make_float4(b0, b1, b2, b3);
        }
    }
}

// ============================================================
// Reduce: sum 4 K-slice partials; emit haloed fp16 val+delta table.
//   g = -1 : {0, val[0]};  g in [0,510]: {val[g], val[g+1]-val[g]}
//   g = 511: {val[511], -val[511]};  g = 512: {0,0}
// ============================================================
__global__ __launch_bounds__(256) void reduce_pk_kernel() {
    int i = blockIdx.x * 256 + threadIdx.x;   // 0 .. W*H-1
    int lane = threadIdx.x & 31;
    int r = i & (H - 1);
    int w = i >> 9;

    float4 a = g_fpart[0][i];
    float4 b = g_fpart[1][i];
    float4 c = g_fpart[2][i];
    float4 d = g_fpart[3][i];
    float s0 = (a.x + b.x) + (c.x + d.x);
    float s1 = (a.y + b.y) + (c.y + d.y);
    float s2 = (a.z + b.z) + (c.z + d.z);
    float s3 = (a.w + b.w) + (c.w + d.w);

    float n0 = __shfl_down_sync(0xffffffffu, s0, 1);
    float n1 = __shfl_down_sync(0xffffffffu, s1, 1);
    float n2 = __shfl_down_sync(0xffffffffu, s2, 1);
    float n3 = __shfl_down_sync(0xffffffffu, s3, 1);
    if (lane == 31) {
        int j = (i + 1 < W * H) ? i + 1 : i;
        float4 a2 = g_fpart[0][j];
        float4 b2 = g_fpart[1][j];
        float4 c2 = g_fpart[2][j];
        float4 d2 = g_fpart[3][j];
        n0 = (a2.x + b2.x) + (c2.x + d2.x);
        n1 = (a2.y + b2.y) + (c2.y + d2.y);
        n2 = (a2.z + b2.z) + (c2.z + d2.z);
        n3 = (a2.w + b2.w) + (c2.w + d2.w);
    }

    bool edge = (r == H - 1);
    float d0 = edge ? -s0 : n0 - s0;
    float d1 = edge ? -s1 : n1 - s1;
    float d2f = edge ? -s2 : n2 - s2;
    float d3 = edge ? -s3 : n3 - s3;

    __half2 v01 = __floats2half2_rn(s0, s1);
    __half2 v23 = __floats2half2_rn(s2, s3);
    __half2 e01 = __floats2half2_rn(d0, d1);
    __half2 e23 = __floats2half2_rn(d2f, d3);
    g_pkt[w * HP + 1 + r] = make_uint4(*(unsigned*)&v01, *(unsigned*)&v23,
                                       *(unsigned*)&e01, *(unsigned*)&e23);

    if (r == 0) {
        __half2 z2 = __floats2half2_rn(0.f, 0.f);
        unsigned zu = *(unsigned*)&z2;
        g_pkt[w * HP + 0] = make_uint4(zu, zu, *(unsigned*)&v01, *(unsigned*)&v23);
    }
    if (edge) {
        g_pkt[w * HP + H + 1] = make_uint4(0u, 0u, 0u, 0u);
    }
}

// ============================================================
// Backprojection: 32x32 tile, 4-way ANGLE SPLIT, 4 angles/barrier,
// half2 accumulation across all 4 angles, ONE fp32 flush per quad.
// ============================================================
__device__ __forceinline__ void stage_group(int wbase, int tid, float X0f, float Y0f,
                                            const float4* scoef, float4* srb,
                                            uint4 (*sb)[WLEN], int w0) {
    int cnt = QW - wbase;
    if (cnt > 4) cnt = 4;
    if (cnt > 0 && tid < cnt * WLEN) {
        int a   = tid / WLEN;            // 0..3
        int idx = tid - a * WLEN;
        int wa  = wbase + a;
        float4 cf = scoef[wa];
        float pymin = fmaf(cf.x, X0f, fmaf(cf.y, Y0f, cf.z)) + cf.w;
        int lo = __float2int_rd(pymin) - 1;
        if (idx == 0)
            srb[wa & (NSTG - 1)] = make_float4(cf.x, cf.y, cf.z - (float)lo,
                                               cf.x * 8.0f);
        int g = lo + idx + 1;            // haloed table index
        unsigned ok = ((unsigned)g < (unsigned)HP) ? 16u : 0u;
        int gc = g < 0 ? 0 : (g > HP - 1 ? HP - 1 : g);
        const uint4* src = g_pkt + ((w0 + wa) * HP + gc);
        unsigned sa = (unsigned)__cvta_generic_to_shared(&sb[wa & (NSTG - 1)][idx]);
        asm volatile("cp.async.cg.shared.global [%0], [%1], 16, %2;\n"
                     :: "r"(sa), "l"(src), "r"(ok));
    }
    asm volatile("cp.async.commit_group;\n" ::: "memory");
}

// 4 angles, half2 accumulation, single fp32 flush
__device__ __forceinline__ void bp_quad(const float4* __restrict__ srb, int wl,
                                        const uint4* __restrict__ b0,
                                        const uint4* __restrict__ b1,
                                        const uint4* __restrict__ b2,
                                        const uint4* __restrict__ b3,
                                        float Xtf, float Ytf,
                                        float acc[4][4]) {
    float4 c0 = srb[(wl    ) & (NSTG - 1)];
    float4 c1 = srb[(wl + 1) & (NSTG - 1)];
    float4 c2 = srb[(wl + 2) & (NSTG - 1)];
    float4 c3 = srb[(wl + 3) & (NSTG - 1)];
    float py0 = fmaf(c0.x, Xtf, fmaf(c0.y, Ytf, c0.z));
    float py1 = fmaf(c1.x, Xtf, fmaf(c1.y, Ytf, c1.z));
    float py2 = fmaf(c2.x, Xtf, fmaf(c2.y, Ytf, c2.z));
    float py3 = fmaf(c3.x, Xtf, fmaf(c3.y, Ytf, c3.z));

    #pragma unroll
    for (int s = 0; s < 4; ++s) {
        int   ya = __float2int_rd(py0);
        float fa = py0 - (float)ya;
        uint4 qa = b0[ya];
        __half2 fa2 = __floats2half2_rn(fa, fa);
        __half2 p01 = __hfma2(u2h(qa.z), fa2, u2h(qa.x));
        __half2 p23 = __hfma2(u2h(qa.w), fa2, u2h(qa.y));

        int   yb = __float2int_rd(py1);
        float fb = py1 - (float)yb;
        uint4 qb = b1[yb];
        __half2 fb2 = __floats2half2_rn(fb, fb);
        p01 = __hadd2(p01, u2h(qb.x));
        p23 = __hadd2(p23, u2h(qb.y));
        p01 = __hfma2(u2h(qb.z), fb2, p01);
        p23 = __hfma2(u2h(qb.w), fb2, p23);

        int   yc = __float2int_rd(py2);
        float fc = py2 - (float)yc;
        uint4 qc = b2[yc];
        __half2 fc2 = __floats2half2_rn(fc, fc);
        p01 = __hadd2(p01, u2h(qc.x));
        p23 = __hadd2(p23, u2h(qc.y));
        p01 = __hfma2(u2h(qc.z), fc2, p01);
        p23 = __hfma2(u2h(qc.w), fc2, p23);

        int   yd = __float2int_rd(py3);
        float fd = py3 - (float)yd;
        uint4 qd = b3[yd];
        __half2 fd2 = __floats2half2_rn(fd, fd);
        p01 = __hadd2(p01, u2h(qd.x));
        p23 = __hadd2(p23, u2h(qd.y));
        p01 = __hfma2(u2h(qd.z), fd2, p01);
        p23 = __hfma2(u2h(qd.w), fd2, p23);

        float2 f01 = __half22float2(p01);
        float2 f23 = __half22float2(p23);
        acc[s][0] += f01.x;
        acc[s][1] += f01.y;
        acc[s][2] += f23.x;
        acc[s][3] += f23.y;
        py0 += c0.w;
        py1 += c1.w;
        py2 += c2.w;
        py3 += c3.w;
    }
}

// 2 angles (epilogue)
__device__ __forceinline__ void bp_pair(const float4* __restrict__ srb, int wl,
                                        const uint4* __restrict__ b0,
                                        const uint4* __restrict__ b1,
                                        float Xtf, float Ytf,
                                        float acc[4][4]) {
    float4 c0 = srb[wl & (NSTG - 1)];
    float4 c1 = srb[(wl + 1) & (NSTG - 1)];
    float py0 = fmaf(c0.x, Xtf, fmaf(c0.y, Ytf, c0.z));
    float py1 = fmaf(c1.x, Xtf, fmaf(c1.y, Ytf, c1.z));

    #pragma unroll
    for (int s = 0; s < 4; ++s) {
        int   ya = __float2int_rd(py0);
        float fa = py0 - (float)ya;
        uint4 qa = b0[ya];
        __half2 fa2 = __floats2half2_rn(fa, fa);
        __half2 p01 = __hfma2(u2h(qa.z), fa2, u2h(qa.x));
        __half2 p23 = __hfma2(u2h(qa.w), fa2, u2h(qa.y));

        int   yb = __float2int_rd(py1);
        float fb = py1 - (float)yb;
        uint4 qb = b1[yb];
        __half2 fb2 = __floats2half2_rn(fb, fb);
        p01 = __hadd2(p01, u2h(qb.x));
        p23 = __hadd2(p23, u2h(qb.y));
        p01 = __hfma2(u2h(qb.z), fb2, p01);
        p23 = __hfma2(u2h(qb.w), fb2, p23);

        float2 f01 = __half22float2(p01);
        float2 f23 = __half22float2(p23);
        acc[s][0] += f01.x;
        acc[s][1] += f01.y;
        acc[s][2] += f23.x;
        acc[s][3] += f23.y;
        py0 += c0.w;
        py1 += c1.w;
    }
}

__global__ __launch_bounds__(256) void backproj_kernel(const float* __restrict__ t_y) {
    __shared__ float4 scoef[QW];
    __shared__ float4 srb[NSTG];
    __shared__ uint4  sb[NSTG][WLEN];

    int tid  = threadIdx.x;
    int lane = tid & 31;
    int warp = tid >> 5;
    int lx = lane >> 2;       // 0..7
    int ly = lane & 3;        // 0..3

    int z  = blockIdx.z;
    int w0 = z * QW;

    if (tid < QW) {
        int w = w0 + tid;
        float cosv =  256.0f * __ldg(&t_y[w * DD + 256 * D + 257]);
        float sinv = -256.0f * __ldg(&t_y[w * DD + 257 * D + 256]);
        const float s = 255.5f / 256.0f;
        float A = -s * sinv;
        float B =  s * cosv;
        float C0 = 255.5f - 256.0f * B - 256.0f * A;
        float minAB = fminf(A * 31.0f, 0.0f) + fminf(B * 31.0f, 0.0f);
        scoef[tid] = make_float4(A, B, C0, minAB);
    }
    __syncthreads();

    int X0 = blockIdx.x * 32;
    int Y0 = blockIdx.y * 32;
    float X0f = (float)X0, Y0f = (float)Y0;

    int Xt = X0 + lx;                 // + s*8 per slot
    int Yt = Y0 + warp * 4 + ly;
    float Xtf = (float)Xt, Ytf = (float)Yt;

    float acc[4][4] = {};             // [slot][batch]

    // prologue: stage groups (0-3), (4-7)
    stage_group(0, tid, X0f, Y0f, scoef, srb, sb, w0);
    stage_group(4, tid, X0f, Y0f, scoef, srb, sb, w0);

    // main loop: 22 iterations x 4 angles (covers 0..87)
    for (int wl = 0; wl < 88; wl += 4) {
        asm volatile("cp.async.wait_group 1;\n" ::: "memory");
        __syncthreads();

        stage_group(wl + 8, tid, X0f, Y0f, scoef, srb, sb, w0);

        bp_quad(srb, wl,
                sb[(wl    ) & (NSTG - 1)], sb[(wl + 1) & (NSTG - 1)],
                sb[(wl + 2) & (NSTG - 1)], sb[(wl + 3) & (NSTG - 1)],
                Xtf, Ytf, acc);
    }

    // epilogue: angles 88, 89
    asm volatile("cp.async.wait_group 0;\n" ::: "memory");
    __syncthreads();
    bp_pair(srb, 88, sb[88 & (NSTG - 1)], sb[89 & (NSTG - 1)], Xtf, Ytf, acc);

    float* pout = g_part[z];
    #pragma unroll
    for (int s = 0; s < 4; ++s) {
        int X = Xt + s * 8;
        int o = X * D + Yt;
        pout[0 * DD + o] = acc[s][0];
        pout[1 * DD + o] = acc[s][1];
        pout[2 * DD + o] = acc[s][2];
        pout[3 * DD + o] = acc[s][3];
    }
}

// ============================================================
// Combine: out = (p0 + p1 + p2 + p3) * scale   (float4)
// ============================================================
__global__ __launch_bounds__(256) void combine_kernel(float* __restrict__ out) {
    const float scale = 0.004363323129985824f;  // pi / 720
    int i = blockIdx.x * 256 + threadIdx.x;
    float4 a = ((const float4*)g_part[0])[i];
    float4 b = ((const float4*)g_part[1])[i];
    float4 c = ((const float4*)g_part[2])[i];
    float4 d = ((const float4*)g_part[3])[i];
    float4 r;
    r.x = ((a.x + b.x) + (c.x + d.x)) * scale;
    r.y = ((a.y + b.y) + (c.y + d.y)) * scale;
    r.z = ((a.z + b.z) + (c.z + d.z)) * scale;
    r.w = ((a.w + b.w) + (c.w + d.w)) * scale;
    ((float4*)out)[i] = r;
}

extern "C" void kernel_launch(void* const* d_in, const int* in_sizes, int n_in,
                              void* d_out, int out_size) {
    const float* radon = (const float*)d_in[0];
    const float* hG    = (const float*)d_in[1];
    const float* t_y   = (const float*)d_in[2];
    float* out = (float*)d_out;

    filter_kernel<<<dim3(8, 23, KSL), 256>>>(radon, hG);
    reduce_pk_kernel<<<(W * H) / 256, 256>>>();
    backproj_kernel<<<dim3(16, 16, 4), 256>>>(t_y);
    combine_kernel<<<(NB * DD / 4) / 256, 256>>>(out);
}

// round 16
// speedup vs baseline: 1.2797x; 1.0347x over previous
#include <cuda_runtime.h>
#include <cuda_fp16.h>
#include <cstdint>

#define NB 4
#define H  512
#define HP (H + 2)         // haloed column length (g in [-1, 512])
#define W  360
#define D  512
#define HW (H*W)           // 184320
#define DD (D*D)           // 262144
#define WLEN 48
#define NSTG 16            // ring buffers (groups of 4, 3 groups live max)
#define QW 90              // angles per backproj CTA (4-way angle split)
#define KSL 4              // filter K-slices
#define KCH (H / KSL)      // 128 k per slice

// ---- device scratch (no allocations allowed) ----
__device__ float4 g_fpart[KSL][W * H];  // fp32 filter partials per K-slice
__device__ uint4  g_pkt[W * HP];        // fp16 val+delta, haloed: {v01, v23, d01, d23}
__device__ uint2  g_parth[4][DD];       // fp16-packed backproj partials {h2(b0,b1), h2(b2,b3)}

// ---- packed f32x2 helpers (FFMA2) ----
__device__ __forceinline__ unsigned long long pk2(float a, float b) {
    unsigned long long r;
    asm("mov.b64 %0, {%1, %2};" : "=l"(r) : "f"(a), "f"(b));
    return r;
}
__device__ __forceinline__ void upk2(unsigned long long v, float &a, float &b) {
    asm("mov.b64 {%0, %1}, %2;" : "=f"(a), "=f"(b) : "l"(v));
}
__device__ __forceinline__ void ffma2(unsigned long long &acc,
                                      unsigned long long a, unsigned long long b) {
    asm("fma.rn.f32x2 %0, %1, %2, %0;" : "+l"(acc) : "l"(a), "l"(b));
}
__device__ __forceinline__ __half2 u2h(unsigned u) { return *(__half2*)&u; }

// ============================================================
// Filter (K-split): C_z[i,c] = sum_{j in slice z} hG[(j-i-257)&511] * X[j,c]
// BM=64, BN=64, K=128/slice, grid (8,23,KSL)=736 CTAs.
// ============================================================
__global__ __launch_bounds__(256) void filter_kernel(const float* __restrict__ x,
                                                     const float* __restrict__ hG) {
    __shared__ float hs[512];
    __shared__ float Fs[16][64];
    __shared__ float Xs[16][64];

    int tid = threadIdx.x;
    hs[tid]       = hG[tid];
    hs[tid + 256] = hG[tid + 256];

    int tx = tid & 15;
    int ty = tid >> 4;
    int iblk = blockIdx.x * 64;
    int cblk = blockIdx.y * 64;
    int kbase = blockIdx.z * KCH;

    int lk  = ty;
    int lo4 = tx * 4;

    int wst = (cblk + lo4) >> 2;
    bool okw = (wst < W);
    const float* Xg = x + wst;

    int jb0 = -(iblk + lo4) - 257;

    __syncthreads();

    float4 fv;
    {
        int b = jb0 + kbase + lk;
        fv.x = hs[(b    ) & 511];
        fv.y = hs[(b - 1) & 511];
        fv.z = hs[(b - 2) & 511];
        fv.w = hs[(b - 3) & 511];
    }
    float xv0 = 0.f, xv1 = 0.f, xv2 = 0.f, xv3 = 0.f;
    if (okw) {
        xv0 = Xg[0 * HW + (kbase + lk) * W];
        xv1 = Xg[1 * HW + (kbase + lk) * W];
        xv2 = Xg[2 * HW + (kbase + lk) * W];
        xv3 = Xg[3 * HW + (kbase + lk) * W];
    }

    unsigned long long acc2[4][2] = {};

    for (int kk = 0; kk < KCH; kk += 16) {
        __syncthreads();
        *(float4*)&Fs[lk][lo4] = fv;
        Xs[lk][lo4 + 0] = xv0;
        Xs[lk][lo4 + 1] = xv1;
        Xs[lk][lo4 + 2] = xv2;
        Xs[lk][lo4 + 3] = xv3;
        __syncthreads();

        int kn = kk + 16;
        if (kn < KCH) {
            int b = jb0 + kbase + kn + lk;
            fv.x = hs[(b    ) & 511];
            fv.y = hs[(b - 1) & 511];
            fv.z = hs[(b - 2) & 511];
            fv.w = hs[(b - 3) & 511];
            if (okw) {
                xv0 = Xg[0 * HW + (kbase + kn + lk) * W];
                xv1 = Xg[1 * HW + (kbase + kn + lk) * W];
                xv2 = Xg[2 * HW + (kbase + kn + lk) * W];
                xv3 = Xg[3 * HW + (kbase + kn + lk) * W];
            }
        }

        #pragma unroll
        for (int k = 0; k < 16; ++k) {
            float4 a  = *(const float4*)&Fs[k][tx * 4];
            float4 b4 = *(const float4*)&Xs[k][ty * 4];
            unsigned long long b01 = pk2(b4.x, b4.y);
            unsigned long long b23 = pk2(b4.z, b4.w);
            unsigned long long ax = pk2(a.x, a.x);
            unsigned long long ay = pk2(a.y, a.y);
            unsigned long long az = pk2(a.z, a.z);
            unsigned long long aw = pk2(a.w, a.w);
            ffma2(acc2[0][0], ax, b01);  ffma2(acc2[0][1], ax, b23);
            ffma2(acc2[1][0], ay, b01);  ffma2(acc2[1][1], ay, b23);
            ffma2(acc2[2][0], az, b01);  ffma2(acc2[2][1], az, b23);
            ffma2(acc2[3][0], aw, b01);  ffma2(acc2[3][1], aw, b23);
        }
    }

    int wout = (cblk >> 2) + ty;
    if (wout < W) {
        float4* pout = g_fpart[blockIdx.z];
        #pragma unroll
        for (int ii = 0; ii < 4; ++ii) {
            float b0, b1, b2, b3;
            upk2(acc2[ii][0], b0, b1);
            upk2(acc2[ii][1], b2, b3);
            pout[wout * H + iblk + tx * 4 + ii] = make_float4(b0, b1, b2, b3);
        }
    }
}

// ============================================================
// Reduce: sum 4 K-slice partials; emit haloed fp16 val+delta table.
//   g = -1 : {0, val[0]};  g in [0,510]: {val[g], val[g+1]-val[g]}
//   g = 511: {val[511], -val[511]};  g = 512: {0,0}
// ============================================================
__global__ __launch_bounds__(256) void reduce_pk_kernel() {
    int i = blockIdx.x * 256 + threadIdx.x;   // 0 .. W*H-1
    int lane = threadIdx.x & 31;
    int r = i & (H - 1);
    int w = i >> 9;

    float4 a = g_fpart[0][i];
    float4 b = g_fpart[1][i];
    float4 c = g_fpart[2][i];
    float4 d = g_fpart[3][i];
    float s0 = (a.x + b.x) + (c.x + d.x);
    float s1 = (a.y + b.y) + (c.y + d.y);
    float s2 = (a.z + b.z) + (c.z + d.z);
    float s3 = (a.w + b.w) + (c.w + d.w);

    float n0 = __shfl_down_sync(0xffffffffu, s0, 1);
    float n1 = __shfl_down_sync(0xffffffffu, s1, 1);
    float n2 = __shfl_down_sync(0xffffffffu, s2, 1);
    float n3 = __shfl_down_sync(0xffffffffu, s3, 1);
    if (lane == 31) {
        int j = (i + 1 < W * H) ? i + 1 : i;
        float4 a2 = g_fpart[0][j];
        float4 b2 = g_fpart[1][j];
        float4 c2 = g_fpart[2][j];
        float4 d2 = g_fpart[3][j];
        n0 = (a2.x + b2.x) + (c2.x + d2.x);
        n1 = (a2.y + b2.y) + (c2.y + d2.y);
        n2 = (a2.z + b2.z) + (c2.z + d2.z);
        n3 = (a2.w + b2.w) + (c2.w + d2.w);
    }

    bool edge = (r == H - 1);
    float d0 = edge ? -s0 : n0 - s0;
    float d1 = edge ? -s1 : n1 - s1;
    float d2f = edge ? -s2 : n2 - s2;
    float d3 = edge ? -s3 : n3 - s3;

    __half2 v01 = __floats2half2_rn(s0, s1);
    __half2 v23 = __floats2half2_rn(s2, s3);
    __half2 e01 = __floats2half2_rn(d0, d1);
    __half2 e23 = __floats2half2_rn(d2f, d3);
    g_pkt[w * HP + 1 + r] = make_uint4(*(unsigned*)&v01, *(unsigned*)&v23,
                                       *(unsigned*)&e01, *(unsigned*)&e23);

    if (r == 0) {
        __half2 z2 = __floats2half2_rn(0.f, 0.f);
        unsigned zu = *(unsigned*)&z2;
        g_pkt[w * HP + 0] = make_uint4(zu, zu, *(unsigned*)&v01, *(unsigned*)&v23);
    }
    if (edge) {
        g_pkt[w * HP + H + 1] = make_uint4(0u, 0u, 0u, 0u);
    }
}

// ============================================================
// Backprojection: 32x32 tile, 4-way ANGLE SPLIT, 4 angles/barrier,
// half2 accumulation per quad, ONE fp32 flush per quad.
// Partials stored fp16-packed (uint2 per pixel).
// ============================================================
__device__ __forceinline__ void stage_group(int wbase, int tid, float X0f, float Y0f,
                                            const float4* scoef, float4* srb,
                                            uint4 (*sb)[WLEN], int w0) {
    int cnt = QW - wbase;
    if (cnt > 4) cnt = 4;
    if (cnt > 0 && tid < cnt * WLEN) {
        int a   = tid / WLEN;            // 0..3
        int idx = tid - a * WLEN;
        int wa  = wbase + a;
        float4 cf = scoef[wa];
        float pymin = fmaf(cf.x, X0f, fmaf(cf.y, Y0f, cf.z)) + cf.w;
        int lo = __float2int_rd(pymin) - 1;
        if (idx == 0)
            srb[wa & (NSTG - 1)] = make_float4(cf.x, cf.y, cf.z - (float)lo,
                                               cf.x * 8.0f);
        int g = lo + idx + 1;            // haloed table index
        unsigned ok = ((unsigned)g < (unsigned)HP) ? 16u : 0u;
        int gc = g < 0 ? 0 : (g > HP - 1 ? HP - 1 : g);
        const uint4* src = g_pkt + ((w0 + wa) * HP + gc);
        unsigned sa = (unsigned)__cvta_generic_to_shared(&sb[wa & (NSTG - 1)][idx]);
        asm volatile("cp.async.cg.shared.global [%0], [%1], 16, %2;\n"
                     :: "r"(sa), "l"(src), "r"(ok));
    }
    asm volatile("cp.async.commit_group;\n" ::: "memory");
}

// 4 angles, half2 accumulation, single fp32 flush
__device__ __forceinline__ void bp_quad(const float4* __restrict__ srb, int wl,
                                        const uint4* __restrict__ b0,
                                        const uint4* __restrict__ b1,
                                        const uint4* __restrict__ b2,
                                        const uint4* __restrict__ b3,
                                        float Xtf, float Ytf,
                                        float acc[4][4]) {
    float4 c0 = srb[(wl    ) & (NSTG - 1)];
    float4 c1 = srb[(wl + 1) & (NSTG - 1)];
    float4 c2 = srb[(wl + 2) & (NSTG - 1)];
    float4 c3 = srb[(wl + 3) & (NSTG - 1)];
    float py0 = fmaf(c0.x, Xtf, fmaf(c0.y, Ytf, c0.z));
    float py1 = fmaf(c1.x, Xtf, fmaf(c1.y, Ytf, c1.z));
    float py2 = fmaf(c2.x, Xtf, fmaf(c2.y, Ytf, c2.z));
    float py3 = fmaf(c3.x, Xtf, fmaf(c3.y, Ytf, c3.z));

    #pragma unroll
    for (int s = 0; s < 4; ++s) {
        int   ya = __float2int_rd(py0);
        float fa = py0 - (float)ya;
        uint4 qa = b0[ya];
        __half2 fa2 = __floats2half2_rn(fa, fa);
        __half2 p01 = __hfma2(u2h(qa.z), fa2, u2h(qa.x));
        __half2 p23 = __hfma2(u2h(qa.w), fa2, u2h(qa.y));

        int   yb = __float2int_rd(py1);
        float fb = py1 - (float)yb;
        uint4 qb = b1[yb];
        __half2 fb2 = __floats2half2_rn(fb, fb);
        p01 = __hadd2(p01, u2h(qb.x));
        p23 = __hadd2(p23, u2h(qb.y));
        p01 = __hfma2(u2h(qb.z), fb2, p01);
        p23 = __hfma2(u2h(qb.w), fb2, p23);

        int   yc = __float2int_rd(py2);
        float fc = py2 - (float)yc;
        uint4 qc = b2[yc];
        __half2 fc2 = __floats2half2_rn(fc, fc);
        p01 = __hadd2(p01, u2h(qc.x));
        p23 = __hadd2(p23, u2h(qc.y));
        p01 = __hfma2(u2h(qc.z), fc2, p01);
        p23 = __hfma2(u2h(qc.w), fc2, p23);

        int   yd = __float2int_rd(py3);
        float fd = py3 - (float)yd;
        uint4 qd = b3[yd];
        __half2 fd2 = __floats2half2_rn(fd, fd);
        p01 = __hadd2(p01, u2h(qd.x));
        p23 = __hadd2(p23, u2h(qd.y));
        p01 = __hfma2(u2h(qd.z), fd2, p01);
        p23 = __hfma2(u2h(qd.w), fd2, p23);

        float2 f01 = __half22float2(p01);
        float2 f23 = __half22float2(p23);
        acc[s][0] += f01.x;
        acc[s][1] += f01.y;
        acc[s][2] += f23.x;
        acc[s][3] += f23.y;
        py0 += c0.w;
        py1 += c1.w;
        py2 += c2.w;
        py3 += c3.w;
    }
}

// 2 angles (epilogue)
__device__ __forceinline__ void bp_pair(const float4* __restrict__ srb, int wl,
                                        const uint4* __restrict__ b0,
                                        const uint4* __restrict__ b1,
                                        float Xtf, float Ytf,
                                        float acc[4][4]) {
    float4 c0 = srb[wl & (NSTG - 1)];
    float4 c1 = srb[(wl + 1) & (NSTG - 1)];
    float py0 = fmaf(c0.x, Xtf, fmaf(c0.y, Ytf, c0.z));
    float py1 = fmaf(c1.x, Xtf, fmaf(c1.y, Ytf, c1.z));

    #pragma unroll
    for (int s = 0; s < 4; ++s) {
        int   ya = __float2int_rd(py0);
        float fa = py0 - (float)ya;
        uint4 qa = b0[ya];
        __half2 fa2 = __floats2half2_rn(fa, fa);
        __half2 p01 = __hfma2(u2h(qa.z), fa2, u2h(qa.x));
        __half2 p23 = __hfma2(u2h(qa.w), fa2, u2h(qa.y));

        int   yb = __float2int_rd(py1);
        float fb = py1 - (float)yb;
        uint4 qb = b1[yb];
        __half2 fb2 = __floats2half2_rn(fb, fb);
        p01 = __hadd2(p01, u2h(qb.x));
        p23 = __hadd2(p23, u2h(qb.y));
        p01 = __hfma2(u2h(qb.z), fb2, p01);
        p23 = __hfma2(u2h(qb.w), fb2, p23);

        float2 f01 = __half22float2(p01);
        float2 f23 = __half22float2(p23);
        acc[s][0] += f01.x;
        acc[s][1] += f01.y;
        acc[s][2] += f23.x;
        acc[s][3] += f23.y;
        py0 += c0.w;
        py1 += c1.w;
    }
}

__global__ __launch_bounds__(256) void backproj_kernel(const float* __restrict__ t_y) {
    __shared__ float4 scoef[QW];
    __shared__ float4 srb[NSTG];
    __shared__ uint4  sb[NSTG][WLEN];

    int tid  = threadIdx.x;
    int lane = tid & 31;
    int warp = tid >> 5;
    int lx = lane >> 2;       // 0..7
    int ly = lane & 3;        // 0..3

    int z  = blockIdx.z;
    int w0 = z * QW;

    if (tid < QW) {
        int w = w0 + tid;
        float cosv =  256.0f * __ldg(&t_y[w * DD + 256 * D + 257]);
        float sinv = -256.0f * __ldg(&t_y[w * DD + 257 * D + 256]);
        const float s = 255.5f / 256.0f;
        float A = -s * sinv;
        float B =  s * cosv;
        float C0 = 255.5f - 256.0f * B - 256.0f * A;
        float minAB = fminf(A * 31.0f, 0.0f) + fminf(B * 31.0f, 0.0f);
        scoef[tid] = make_float4(A, B, C0, minAB);
    }
    __syncthreads();

    int X0 = blockIdx.x * 32;
    int Y0 = blockIdx.y * 32;
    float X0f = (float)X0, Y0f = (float)Y0;

    int Xt = X0 + lx;                 // + s*8 per slot
    int Yt = Y0 + warp * 4 + ly;
    float Xtf = (float)Xt, Ytf = (float)Yt;

    float acc[4][4] = {};             // [slot][batch]

    // prologue: stage groups (0-3), (4-7)
    stage_group(0, tid, X0f, Y0f, scoef, srb, sb, w0);
    stage_group(4, tid, X0f, Y0f, scoef, srb, sb, w0);

    // main loop: 22 iterations x 4 angles (covers 0..87)
    for (int wl = 0; wl < 88; wl += 4) {
        asm volatile("cp.async.wait_group 1;\n" ::: "memory");
        __syncthreads();

        stage_group(wl + 8, tid, X0f, Y0f, scoef, srb, sb, w0);

        bp_quad(srb, wl,
                sb[(wl    ) & (NSTG - 1)], sb[(wl + 1) & (NSTG - 1)],
                sb[(wl + 2) & (NSTG - 1)], sb[(wl + 3) & (NSTG - 1)],
                Xtf, Ytf, acc);
    }

    // epilogue: angles 88, 89
    asm volatile("cp.async.wait_group 0;\n" ::: "memory");
    __syncthreads();
    bp_pair(srb, 88, sb[88 & (NSTG - 1)], sb[89 & (NSTG - 1)], Xtf, Ytf, acc);

    uint2* pout = g_parth[z];
    #pragma unroll
    for (int s = 0; s < 4; ++s) {
        int X = Xt + s * 8;
        int o = X * D + Yt;
        __half2 h01 = __floats2half2_rn(acc[s][0], acc[s][1]);
        __half2 h23 = __floats2half2_rn(acc[s][2], acc[s][3]);
        pout[o] = make_uint2(*(unsigned*)&h01, *(unsigned*)&h23);
    }
}

// ============================================================
// Combine: out[n*DD + i] = (sum_z parth[z][i].batch_n) * scale
// fp16-packed partials, fp32 accumulation, coalesced plane writes.
// ============================================================
__global__ __launch_bounds__(256) void combine_kernel(float* __restrict__ out) {
    const float scale = 0.004363323129985824f;  // pi / 720
    int i = blockIdx.x * 256 + threadIdx.x;     // pixel index
    float a0 = 0.f, a1 = 0.f, a2 = 0.f, a3 = 0.f;
    #pragma unroll
    for (int z = 0; z < 4; ++z) {
        uint2 q = g_parth[z][i];
        float2 f01 = __half22float2(u2h(q.x));
        float2 f23 = __half22float2(u2h(q.y));
        a0 += f01.x;
        a1 += f01.y;
        a2 += f23.x;
        a3 += f23.y;
    }
    out[0 * DD + i] = a0 * scale;
    out[1 * DD + i] = a1 * scale;
    out[2 * DD + i] = a2 * scale;
    out[3 * DD + i] = a3 * scale;
}

extern "C" void kernel_launch(void* const* d_in, const int* in_sizes, int n_in,
                              void* d_out, int out_size) {
    const float* radon = (const float*)d_in[0];
    const float* hG    = (const float*)d_in[1];
    const float* t_y   = (const float*)d_in[2];
    float* out = (float*)d_out;

    filter_kernel<<<dim3(8, 23, KSL), 256>>>(radon, hG);
    reduce_pk_kernel<<<(W * H) / 256, 256>>>();
    backproj_kernel<<<dim3(16, 16, 4), 256>>>(t_y);
    combine_kernel<<<DD / 256, 256>>>(out);
}